// round 6
// baseline (speedup 1.0000x reference)
#include <cuda_runtime.h>
#include <math.h>

#define NN 100000
#define NE 3200000
#define NF 128
#define HH 16
#define NC 10
#define SCAN_T 1024
#define CHUNK ((NN + SCAN_T - 1) / SCAN_T)   // 98

// ---------------- device scratch ----------------
__device__ int   g_cnt1[NN];
__device__ int   g_cnt2[NN];
__device__ int   g_cur1[NN];
__device__ int   g_cur2[NN];
__device__ int   g_off1[NN + 1];
__device__ int   g_off2[NN + 1];
__device__ int   g_adj1[NE];     // src node per edge, grouped by dst (graph 1)
__device__ int   g_adj2[NE];     // graph 2
__device__ float g_dinv1[NN];
__device__ float g_dinv2[NN];
__device__ __align__(16) float g_y1[NN * 16];   // dinv1[i] * (x @ W1)[i]
__device__ __align__(16) float g_y2[NN * 16];
__device__ __align__(16) float g_acc1[NN * 16];
__device__ __align__(16) float g_acc2[NN * 16];
__device__ __align__(16) float g_yz[NN * 12];   // dinv1[i] * (h @ W4)[i], stride 12
__device__ __align__(16) float g_acc3[NN * 12];

// ---------------- zero counters ----------------
__global__ void k_zero() {
    int i = blockIdx.x * blockDim.x + threadIdx.x;
    int stride = gridDim.x * blockDim.x;
    for (int t = i; t < NN; t += stride) {
        g_cnt1[t] = 0; g_cnt2[t] = 0; g_cur1[t] = 0; g_cur2[t] = 0;
    }
}

// ---------------- count in-degree (both graphs) ----------------
__global__ void k_count(const int* __restrict__ dst1,
                        const int* __restrict__ dst2) {
    int e = blockIdx.x * blockDim.x + threadIdx.x;
    if (e < NE) {
        atomicAdd(&g_cnt1[dst1[e]], 1);
    } else if (e < 2 * NE) {
        atomicAdd(&g_cnt2[dst2[e - NE]], 1);
    }
}

// ---------------- exclusive scan of counts -> offsets, plus dinv -------------
// one block per graph, SCAN_T threads, serial chunk per thread + block scan.
__global__ void k_scan() {
    __shared__ int part[SCAN_T];
    const int* cnt = blockIdx.x ? g_cnt2 : g_cnt1;
    int* off       = blockIdx.x ? g_off2 : g_off1;
    float* dinv    = blockIdx.x ? g_dinv2 : g_dinv1;
    int t = threadIdx.x;
    int lo = t * CHUNK, hi = min(lo + CHUNK, NN);

    int s = 0;
    for (int i = lo; i < hi; i++) s += cnt[i];
    part[t] = s;
    __syncthreads();
    // Hillis-Steele inclusive scan
    for (int d = 1; d < SCAN_T; d <<= 1) {
        int v = (t >= d) ? part[t - d] : 0;
        __syncthreads();
        part[t] += v;
        __syncthreads();
    }
    int run = part[t] - s;   // exclusive prefix for this chunk
    for (int i = lo; i < hi; i++) {
        off[i] = run;
        int c = cnt[i];
        run += c;
        dinv[i] = rsqrtf((float)(c + 1));
    }
    if (t == SCAN_T - 1) off[NN] = run;
}

// ---------------- place: adj[off[dst] + slot] = src (both graphs) ------------
__global__ void k_place(const int* __restrict__ src1, const int* __restrict__ dst1,
                        const int* __restrict__ src2, const int* __restrict__ dst2) {
    int e = blockIdx.x * blockDim.x + threadIdx.x;
    if (e < NE) {
        int d = dst1[e];
        int pos = g_off1[d] + atomicAdd(&g_cur1[d], 1);
        g_adj1[pos] = src1[e];
    } else if (e < 2 * NE) {
        int ee = e - NE;
        int d = dst2[ee];
        int pos = g_off2[d] + atomicAdd(&g_cur2[d], 1);
        g_adj2[pos] = src2[ee];
    }
}

// ---------------- fused dual GEMM: y1 = dinv1*(x@W1), y2 = dinv2*(x@W2) ------
__global__ void k_gemm(const float* __restrict__ x,
                       const float* __restrict__ W1,
                       const float* __restrict__ W2) {
    extern __shared__ float s_mem[];
    float* Ws = s_mem;              // [128][32]
    float* xs = s_mem + NF * 32;    // [128][129] padded

    int tid = threadIdx.x;
    for (int idx = tid; idx < NF * 32; idx += 128) {
        int k = idx >> 5, j = idx & 31;
        Ws[idx] = (j < HH) ? W1[k * HH + j] : W2[k * HH + (j - HH)];
    }
    int nb = blockIdx.x * 128;
    for (int idx = tid; idx < 128 * NF; idx += 128) {
        int node = idx >> 7, k = idx & 127;
        int gi = nb + node;
        xs[node * 129 + k] = (gi < NN) ? x[(size_t)gi * NF + k] : 0.f;
    }
    __syncthreads();

    int i = nb + tid;
    if (i >= NN) return;

    float acc[32];
#pragma unroll
    for (int j = 0; j < 32; j++) acc[j] = 0.f;

    const float* xr = &xs[tid * 129];
#pragma unroll 4
    for (int k = 0; k < NF; k++) {
        float xk = xr[k];
        const float* wrow = &Ws[k * 32];
#pragma unroll
        for (int j = 0; j < 32; j++) acc[j] += xk * wrow[j];
    }

    float d1 = g_dinv1[i];
    float d2 = g_dinv2[i];
    float* o1 = &g_y1[(size_t)i * 16];
    float* o2 = &g_y2[(size_t)i * 16];
#pragma unroll
    for (int j = 0; j < 16; j++) {
        o1[j] = d1 * acc[j];
        o2[j] = d2 * acc[16 + j];
    }
}

// ---------------- warp-per-node gather, 16 channels --------------------------
// lane = slot*4 + q : 8 edge slots x 4 channel-quads. Register accumulate,
// shfl-tree over slots, STG.128 by slot 0. No atomics.
__global__ void k_gather16(const int* __restrict__ off,
                           const int* __restrict__ adj,
                           const float* __restrict__ y,
                           float* __restrict__ acc) {
    int w = (blockIdx.x * blockDim.x + threadIdx.x) >> 5;
    if (w >= NN) return;
    int lane = threadIdx.x & 31;
    int q = lane & 3, slot = lane >> 2;

    int beg = off[w], end = off[w + 1];
    float ax = 0.f, ay = 0.f, az = 0.f, aw = 0.f;
    for (int p = beg + slot; p < end; p += 8) {
        int s = adj[p];
        float4 v = *(const float4*)(y + (size_t)s * 16 + q * 4);
        ax += v.x; ay += v.y; az += v.z; aw += v.w;
    }
#pragma unroll
    for (int o = 16; o >= 4; o >>= 1) {
        ax += __shfl_xor_sync(0xffffffffu, ax, o);
        ay += __shfl_xor_sync(0xffffffffu, ay, o);
        az += __shfl_xor_sync(0xffffffffu, az, o);
        aw += __shfl_xor_sync(0xffffffffu, aw, o);
    }
    if (slot == 0)
        *(float4*)(acc + (size_t)w * 16 + q * 4) = make_float4(ax, ay, az, aw);
}

// ---------------- warp-per-node gather, 10 channels (stride 12) --------------
__global__ void k_gather10() {
    int w = (blockIdx.x * blockDim.x + threadIdx.x) >> 5;
    if (w >= NN) return;
    int lane = threadIdx.x & 31;
    int q = lane & 3, slot = lane >> 2;

    int beg = g_off1[w], end = g_off1[w + 1];
    float ax = 0.f, ay = 0.f, az = 0.f, aw = 0.f;
    if (q < 3) {
        for (int p = beg + slot; p < end; p += 8) {
            int s = g_adj1[p];
            float4 v = *(const float4*)(&g_yz[(size_t)s * 12] + q * 4);
            ax += v.x; ay += v.y; az += v.z; aw += v.w;
        }
    }
#pragma unroll
    for (int o = 16; o >= 4; o >>= 1) {
        ax += __shfl_xor_sync(0xffffffffu, ax, o);
        ay += __shfl_xor_sync(0xffffffffu, ay, o);
        az += __shfl_xor_sync(0xffffffffu, az, o);
        aw += __shfl_xor_sync(0xffffffffu, aw, o);
    }
    if (slot == 0 && q < 3)
        *(float4*)(&g_acc3[(size_t)w * 12] + q * 4) = make_float4(ax, ay, az, aw);
}

// ---------------- combine: relu epilogues, concat, h @ W4, pre-scale ---------
__global__ void k_combine(const float* __restrict__ b1,
                          const float* __restrict__ b2,
                          const float* __restrict__ W4) {
    __shared__ float sW4[32 * NC];
    __shared__ float sb1[HH], sb2[HH];
    int tid = threadIdx.x;
    for (int t = tid; t < 32 * NC; t += blockDim.x) sW4[t] = W4[t];
    if (tid < HH) { sb1[tid] = b1[tid]; sb2[tid] = b2[tid]; }
    __syncthreads();

    int i = blockIdx.x * blockDim.x + tid;
    if (i >= NN) return;

    float d1 = g_dinv1[i], d2 = g_dinv2[i];
    float h[32];
    const float* a1 = &g_acc1[(size_t)i * 16];
    const float* y1 = &g_y1[(size_t)i * 16];
    const float* a2 = &g_acc2[(size_t)i * 16];
    const float* y2 = &g_y2[(size_t)i * 16];
#pragma unroll
    for (int j = 0; j < 16; j++) {
        h[j]      = fmaxf(d1 * (a1[j] + y1[j]) + sb1[j], 0.f);
        h[16 + j] = fmaxf(d2 * (a2[j] + y2[j]) + sb2[j], 0.f);
    }

    float z[NC];
#pragma unroll
    for (int c = 0; c < NC; c++) z[c] = 0.f;
#pragma unroll
    for (int j = 0; j < 32; j++) {
        float hj = h[j];
#pragma unroll
        for (int c = 0; c < NC; c++) z[c] += hj * sW4[j * NC + c];
    }

    float* o = &g_yz[(size_t)i * 12];
#pragma unroll
    for (int c = 0; c < NC; c++) o[c] = d1 * z[c];
    o[10] = 0.f;
    o[11] = 0.f;
}

// ---------------- final: conv3 epilogue + log_softmax ----------------
__global__ void k_final(const float* __restrict__ b4, float* __restrict__ out) {
    __shared__ float sb4[NC];
    if (threadIdx.x < NC) sb4[threadIdx.x] = b4[threadIdx.x];
    __syncthreads();
    int i = blockIdx.x * blockDim.x + threadIdx.x;
    if (i >= NN) return;

    float d1 = g_dinv1[i];
    float l[NC];
    const float* a = &g_acc3[(size_t)i * 12];
    const float* y = &g_yz[(size_t)i * 12];
#pragma unroll
    for (int c = 0; c < NC; c++) l[c] = d1 * (a[c] + y[c]) + sb4[c];

    float m = l[0];
#pragma unroll
    for (int c = 1; c < NC; c++) m = fmaxf(m, l[c]);
    float s = 0.f;
#pragma unroll
    for (int c = 0; c < NC; c++) s += expf(l[c] - m);
    float lse = m + logf(s);
#pragma unroll
    for (int c = 0; c < NC; c++) out[(size_t)i * NC + c] = l[c] - lse;
}

// ---------------- launch ----------------
extern "C" void kernel_launch(void* const* d_in, const int* in_sizes, int n_in,
                              void* d_out, int out_size) {
    const float* x  = (const float*)d_in[0];
    const int*   ei = (const int*)d_in[1];   // [2, NE] int32: row0 src, row1 dst
    const int*   tp = (const int*)d_in[2];
    const float* W1 = (const float*)d_in[3];
    const float* b1 = (const float*)d_in[4];
    const float* W2 = (const float*)d_in[5];
    const float* b2 = (const float*)d_in[6];
    const float* W4 = (const float*)d_in[7];
    const float* b4 = (const float*)d_in[8];
    float* out = (float*)d_out;

    int *p_off1, *p_off2, *p_adj1, *p_adj2;
    float *p_y1, *p_y2, *p_a1, *p_a2;
    cudaGetSymbolAddress((void**)&p_off1, g_off1);
    cudaGetSymbolAddress((void**)&p_off2, g_off2);
    cudaGetSymbolAddress((void**)&p_adj1, g_adj1);
    cudaGetSymbolAddress((void**)&p_adj2, g_adj2);
    cudaGetSymbolAddress((void**)&p_y1, g_y1);
    cudaGetSymbolAddress((void**)&p_y2, g_y2);
    cudaGetSymbolAddress((void**)&p_a1, g_acc1);
    cudaGetSymbolAddress((void**)&p_a2, g_acc2);

    k_zero<<<512, 256>>>();
    k_count<<<(2 * NE + 255) / 256, 256>>>(ei + NE, tp + NE);
    k_scan<<<2, SCAN_T>>>();
    k_place<<<(2 * NE + 255) / 256, 256>>>(ei, ei + NE, tp, tp + NE);

    size_t smem = (size_t)(NF * 32 + 128 * 129) * sizeof(float);  // 82432 B
    cudaFuncSetAttribute(k_gemm, cudaFuncAttributeMaxDynamicSharedMemorySize, (int)smem);
    k_gemm<<<(NN + 127) / 128, 128, smem>>>(x, W1, W2);

    // warp per node: NN*32 threads
    const int GB = (NN * 32 + 255) / 256;
    k_gather16<<<GB, 256>>>(p_off1, p_adj1, p_y1, p_a1);
    k_gather16<<<GB, 256>>>(p_off2, p_adj2, p_y2, p_a2);

    k_combine<<<(NN + 255) / 256, 256>>>(b1, b2, W4);

    k_gather10<<<GB, 256>>>();

    k_final<<<(NN + 255) / 256, 256>>>(b4, out);
}

// round 8
// speedup vs baseline: 1.7554x; 1.7554x over previous
#include <cuda_runtime.h>
#include <math.h>

#define NN 100000
#define NE 3200000
#define NF 128
#define HH 16
#define NC 10

#define GEMM_BLKS ((NN + 127) / 128)                 // 782, 128 nodes per block
#define CNT_BLKS  ((2 * (NE / 4) + 255) / 256)       // 6250, int4 edge loads

// ---------------- device scratch ----------------
__device__ int   g_cnt1[NN];
__device__ int   g_cnt2[NN];
__device__ float g_dinv1[NN];
__device__ float g_dinv2[NN];
__device__ __align__(16) float g_y1[NN * 16];   // dinv1[i]*(x@W1)[i] after k_scale
__device__ __align__(16) float g_y2[NN * 16];
__device__ __align__(16) float g_acc1[NN * 16]; // init = y (self-loop), + scatter
__device__ __align__(16) float g_acc2[NN * 16];
__device__ __align__(16) float g_yz[NN * 12];   // dinv1[i]*(h@W4)[i], stride 12
__device__ __align__(16) float g_acc3[NN * 12]; // init = yz, + scatter

// 16-byte vector reduction straight to L2 (sm_90+).
__device__ __forceinline__ void red_add_v4(float* p, float4 v) {
    asm volatile("red.global.add.v4.f32 [%0], {%1,%2,%3,%4};"
                 :: "l"(__cvta_generic_to_global(p)),
                    "f"(v.x), "f"(v.y), "f"(v.z), "f"(v.w)
                 : "memory");
}

// ---------------- zero degree counters only ----------------
__global__ void k_zero() {
    int i = blockIdx.x * blockDim.x + threadIdx.x;
    int stride = gridDim.x * blockDim.x;
    for (int t = i; t < NN; t += stride) { g_cnt1[t] = 0; g_cnt2[t] = 0; }
}

// ---------------- fused: [blocks 0..GEMM_BLKS) dual GEMM | rest: degree count ----
__global__ void k_fused(const float* __restrict__ x,
                        const float* __restrict__ W1,
                        const float* __restrict__ W2,
                        const int* __restrict__ dst1,
                        const int* __restrict__ dst2) {
    extern __shared__ float s_mem[];
    int tid = threadIdx.x;

    if (blockIdx.x < GEMM_BLKS) {
        float* Ws = s_mem;              // [128][32]
        float* xs = s_mem + NF * 32;    // [128][129] padded

        for (int idx = tid; idx < NF * 32; idx += 256) {
            int k = idx >> 5, j = idx & 31;
            Ws[idx] = (j < HH) ? W1[k * HH + j] : W2[k * HH + (j - HH)];
        }
        int nb = blockIdx.x * 128;
        for (int idx = tid; idx < 128 * NF; idx += 256) {
            int node = idx >> 7, k = idx & 127;
            int gi = nb + node;
            xs[node * 129 + k] = (gi < NN) ? x[(size_t)gi * NF + k] : 0.f;
        }
        __syncthreads();

        int node = tid >> 1, half = tid & 1;
        int i = nb + node;
        if (i >= NN) return;

        float acc[16];
#pragma unroll
        for (int j = 0; j < 16; j++) acc[j] = 0.f;

        const float* xr = &xs[node * 129];
        const float* wbase = &Ws[half * 16];
#pragma unroll 4
        for (int k = 0; k < NF; k++) {
            float xk = xr[k];
            const float* wrow = wbase + k * 32;
#pragma unroll
            for (int j = 0; j < 16; j++) acc[j] += xk * wrow[j];
        }

        float* o = half ? &g_y2[(size_t)i * 16] : &g_y1[(size_t)i * 16];
#pragma unroll
        for (int q = 0; q < 4; q++)
            *(float4*)(o + 4 * q) = make_float4(acc[4 * q], acc[4 * q + 1],
                                                acc[4 * q + 2], acc[4 * q + 3]);
    } else {
        int id = (blockIdx.x - GEMM_BLKS) * 256 + tid;   // int4 index
        const int Q = NE / 4;                             // 800000
        if (id < Q) {
            int4 d = ((const int4*)dst1)[id];
            atomicAdd(&g_cnt1[d.x], 1);
            atomicAdd(&g_cnt1[d.y], 1);
            atomicAdd(&g_cnt1[d.z], 1);
            atomicAdd(&g_cnt1[d.w], 1);
        } else if (id < 2 * Q) {
            int4 d = ((const int4*)dst2)[id - Q];
            atomicAdd(&g_cnt2[d.x], 1);
            atomicAdd(&g_cnt2[d.y], 1);
            atomicAdd(&g_cnt2[d.z], 1);
            atomicAdd(&g_cnt2[d.w], 1);
        }
    }
}

// ---------------- scale: dinv from counts; y *= dinv; acc init = y (self-loop)
// quad layout: 4 lanes per node, coalesced float4.
__global__ void k_scale() {
    unsigned t = blockIdx.x * blockDim.x + threadIdx.x;
    unsigned node = t >> 2;
    int q = t & 3;
    if (node >= NN) return;
    float d1 = rsqrtf((float)(g_cnt1[node] + 1));
    float d2 = rsqrtf((float)(g_cnt2[node] + 1));
    if (q == 0) { g_dinv1[node] = d1; g_dinv2[node] = d2; }
    size_t o = (size_t)node * 16 + q * 4;
    float4 v1 = *(const float4*)(g_y1 + o);
    float4 v2 = *(const float4*)(g_y2 + o);
    v1.x *= d1; v1.y *= d1; v1.z *= d1; v1.w *= d1;
    v2.x *= d2; v2.y *= d2; v2.z *= d2; v2.w *= d2;
    *(float4*)(g_y1 + o) = v1;
    *(float4*)(g_y2 + o) = v2;
    *(float4*)(g_acc1 + o) = v1;   // self-loop seed: y itself (epilogue applies dinv)
    *(float4*)(g_acc2 + o) = v2;
}

// ---------------- quad-per-edge scatter, both graphs in one launch ------------
__global__ void k_scatter16b(const int* __restrict__ src1, const int* __restrict__ dst1,
                             const int* __restrict__ src2, const int* __restrict__ dst2) {
    unsigned t = blockIdx.x * blockDim.x + threadIdx.x;
    unsigned e = t >> 2;
    int q = t & 3;
    if (e < NE) {
        int s = src1[e], d = dst1[e];
        float4 v = *(const float4*)(g_y1 + (size_t)s * 16 + q * 4);
        red_add_v4(g_acc1 + (size_t)d * 16 + q * 4, v);
    } else if (e < 2u * NE) {
        unsigned ee = e - NE;
        int s = src2[ee], d = dst2[ee];
        float4 v = *(const float4*)(g_y2 + (size_t)s * 16 + q * 4);
        red_add_v4(g_acc2 + (size_t)d * 16 + q * 4, v);
    }
}

// ---------------- combine: relu epilogue, concat, h @ W4, write yz + acc3 seed
__global__ void k_combine(const float* __restrict__ b1,
                          const float* __restrict__ b2,
                          const float* __restrict__ W4) {
    __shared__ float sW4[32 * NC];
    __shared__ float sb1[HH], sb2[HH];
    int tid = threadIdx.x;
    for (int t = tid; t < 32 * NC; t += blockDim.x) sW4[t] = W4[t];
    if (tid < HH) { sb1[tid] = b1[tid]; sb2[tid] = b2[tid]; }
    __syncthreads();

    int i = blockIdx.x * blockDim.x + tid;
    if (i >= NN) return;

    float d1 = g_dinv1[i], d2 = g_dinv2[i];
    float h[32];
    const float* a1 = &g_acc1[(size_t)i * 16];
    const float* a2 = &g_acc2[(size_t)i * 16];
#pragma unroll
    for (int j = 0; j < 16; j++) {
        h[j]      = fmaxf(d1 * a1[j] + sb1[j], 0.f);
        h[16 + j] = fmaxf(d2 * a2[j] + sb2[j], 0.f);
    }

    float z[NC];
#pragma unroll
    for (int c = 0; c < NC; c++) z[c] = 0.f;
#pragma unroll
    for (int j = 0; j < 32; j++) {
        float hj = h[j];
#pragma unroll
        for (int c = 0; c < NC; c++) z[c] += hj * sW4[j * NC + c];
    }

    float* o = &g_yz[(size_t)i * 12];
    float* a = &g_acc3[(size_t)i * 12];
#pragma unroll
    for (int c = 0; c < NC; c++) {
        float yz = d1 * z[c];
        o[c] = yz;
        a[c] = yz;          // self-loop seed (epilogue applies dinv)
    }
    o[10] = 0.f; o[11] = 0.f;
    a[10] = 0.f; a[11] = 0.f;
}

// ---------------- 3-lanes-per-edge scatter for 12-padded logits ---------------
__global__ void k_scatter10q(const int* __restrict__ src,
                             const int* __restrict__ dst) {
    unsigned t = blockIdx.x * blockDim.x + threadIdx.x;
    unsigned e = t / 3u;
    int q = (int)(t - e * 3u);
    if (e >= NE) return;
    int s = src[e], d = dst[e];
    float4 v = *(const float4*)(&g_yz[(size_t)s * 12] + q * 4);
    red_add_v4(&g_acc3[(size_t)d * 12] + q * 4, v);
}

// ---------------- final: conv3 epilogue + log_softmax ----------------
__global__ void k_final(const float* __restrict__ b4, float* __restrict__ out) {
    __shared__ float sb4[NC];
    if (threadIdx.x < NC) sb4[threadIdx.x] = b4[threadIdx.x];
    __syncthreads();
    int i = blockIdx.x * blockDim.x + threadIdx.x;
    if (i >= NN) return;

    float d1 = g_dinv1[i];
    float l[NC];
    const float* a = &g_acc3[(size_t)i * 12];
#pragma unroll
    for (int c = 0; c < NC; c++) l[c] = d1 * a[c] + sb4[c];

    float m = l[0];
#pragma unroll
    for (int c = 1; c < NC; c++) m = fmaxf(m, l[c]);
    float s = 0.f;
#pragma unroll
    for (int c = 0; c < NC; c++) s += expf(l[c] - m);
    float lse = m + logf(s);
#pragma unroll
    for (int c = 0; c < NC; c++) out[(size_t)i * NC + c] = l[c] - lse;
}

// ---------------- launch ----------------
extern "C" void kernel_launch(void* const* d_in, const int* in_sizes, int n_in,
                              void* d_out, int out_size) {
    const float* x  = (const float*)d_in[0];
    const int*   ei = (const int*)d_in[1];   // [2, NE] int32: row0 src, row1 dst
    const int*   tp = (const int*)d_in[2];
    const float* W1 = (const float*)d_in[3];
    const float* b1 = (const float*)d_in[4];
    const float* W2 = (const float*)d_in[5];
    const float* b2 = (const float*)d_in[6];
    const float* W4 = (const float*)d_in[7];
    const float* b4 = (const float*)d_in[8];
    float* out = (float*)d_out;

    k_zero<<<256, 256>>>();

    size_t smem = (size_t)(NF * 32 + 128 * 129) * sizeof(float);  // 82432 B
    cudaFuncSetAttribute(k_fused, cudaFuncAttributeMaxDynamicSharedMemorySize, (int)smem);
    k_fused<<<GEMM_BLKS + CNT_BLKS, 256, smem>>>(x, W1, W2, ei + NE, tp + NE);

    k_scale<<<(4 * NN + 255) / 256, 256>>>();

    k_scatter16b<<<(8u * NE + 255) / 256, 256>>>(ei, ei + NE, tp, tp + NE);

    k_combine<<<(NN + 255) / 256, 256>>>(b1, b2, W4);

    k_scatter10q<<<(3u * NE + 255) / 256, 256>>>(ei, ei + NE);

    k_final<<<(NN + 255) / 256, 256>>>(b4, out);
}

// round 9
// speedup vs baseline: 1.7618x; 1.0037x over previous
#include <cuda_runtime.h>
#include <math.h>

#define NN 100000
#define NE 3200000
#define NF 128
#define HH 16
#define NC 10

#define GEMM_BLKS ((NN + 127) / 128)                  // 782, 128 nodes/block, 1 thr/node
#define CNT_BLKS  ((2 * (NE / 4) + 127) / 128)        // 12500, int4 edge loads

// ---------------- device scratch ----------------
__device__ int   g_cnt1[NN];
__device__ int   g_cnt2[NN];
__device__ float g_dinv1[NN];
__device__ float g_dinv2[NN];
__device__ __align__(16) float g_y1[NN * 16];   // dinv1[i]*(x@W1)[i] after k_scale
__device__ __align__(16) float g_y2[NN * 16];
__device__ __align__(16) float g_acc1[NN * 16]; // seed = y (self-loop), + scatter
__device__ __align__(16) float g_acc2[NN * 16];
__device__ __align__(16) float g_yz[NN * 12];   // dinv1[i]*(h@W4)[i], stride 12
__device__ __align__(16) float g_acc3[NN * 12]; // seed = yz, + scatter

// 16-byte vector reduction straight to L2 (sm_90+).
__device__ __forceinline__ void red_add_v4(float* p, float4 v) {
    asm volatile("red.global.add.v4.f32 [%0], {%1,%2,%3,%4};"
                 :: "l"(__cvta_generic_to_global(p)),
                    "f"(v.x), "f"(v.y), "f"(v.z), "f"(v.w)
                 : "memory");
}

// ---------------- zero degree counters only ----------------
__global__ void k_zero() {
    int i = blockIdx.x * blockDim.x + threadIdx.x;
    int stride = gridDim.x * blockDim.x;
    for (int t = i; t < NN; t += stride) { g_cnt1[t] = 0; g_cnt2[t] = 0; }
}

// ---------------- fused: [0..CNT_BLKS) degree count | rest: dual GEMM ----------
// Static 16KB smem only -> count blocks co-reside at high occupancy with GEMM.
// GEMM: 128 thr/block, thread = node, 32 reg accumulators, x streamed via LDG.128,
// W (128x32: W1 cols 0..15 | W2 cols 16..31) broadcast from shared.
__global__ void __launch_bounds__(128) k_fused(
        const float* __restrict__ x,
        const float* __restrict__ W1,
        const float* __restrict__ W2,
        const int* __restrict__ dst1,
        const int* __restrict__ dst2) {
    __shared__ float Ws[NF * 32];
    int tid = threadIdx.x;

    if (blockIdx.x < CNT_BLKS) {
        int id = blockIdx.x * 128 + tid;                 // int4 index
        const int Q = NE / 4;                            // 800000
        if (id < Q) {
            int4 d = ((const int4*)dst1)[id];
            atomicAdd(&g_cnt1[d.x], 1);
            atomicAdd(&g_cnt1[d.y], 1);
            atomicAdd(&g_cnt1[d.z], 1);
            atomicAdd(&g_cnt1[d.w], 1);
        } else if (id < 2 * Q) {
            int4 d = ((const int4*)dst2)[id - Q];
            atomicAdd(&g_cnt2[d.x], 1);
            atomicAdd(&g_cnt2[d.y], 1);
            atomicAdd(&g_cnt2[d.z], 1);
            atomicAdd(&g_cnt2[d.w], 1);
        }
        return;
    }

    // ---- GEMM part ----
    for (int idx = tid; idx < NF * 32; idx += 128) {
        int k = idx >> 5, j = idx & 31;
        Ws[idx] = (j < HH) ? W1[k * HH + j] : W2[k * HH + (j - HH)];
    }
    __syncthreads();

    int i = (blockIdx.x - CNT_BLKS) * 128 + tid;
    if (i >= NN) return;

    float acc[32];
#pragma unroll
    for (int j = 0; j < 32; j++) acc[j] = 0.f;

    const float4* xrow = (const float4*)(x + (size_t)i * NF);
#pragma unroll 2
    for (int kk = 0; kk < NF / 4; kk++) {
        float4 xv = xrow[kk];
        const float* w = &Ws[(kk * 4) * 32];
#pragma unroll
        for (int j = 0; j < 32; j++) acc[j] += xv.x * w[j];
        w += 32;
#pragma unroll
        for (int j = 0; j < 32; j++) acc[j] += xv.y * w[j];
        w += 32;
#pragma unroll
        for (int j = 0; j < 32; j++) acc[j] += xv.z * w[j];
        w += 32;
#pragma unroll
        for (int j = 0; j < 32; j++) acc[j] += xv.w * w[j];
    }

    float* o1 = &g_y1[(size_t)i * 16];
    float* o2 = &g_y2[(size_t)i * 16];
#pragma unroll
    for (int q = 0; q < 4; q++) {
        *(float4*)(o1 + 4 * q) = make_float4(acc[4 * q], acc[4 * q + 1],
                                             acc[4 * q + 2], acc[4 * q + 3]);
        *(float4*)(o2 + 4 * q) = make_float4(acc[16 + 4 * q], acc[16 + 4 * q + 1],
                                             acc[16 + 4 * q + 2], acc[16 + 4 * q + 3]);
    }
}

// ---------------- scale: dinv from counts; y *= dinv; acc seed = y -------------
// quad layout: 4 lanes per node, coalesced float4.
__global__ void k_scale() {
    unsigned t = blockIdx.x * blockDim.x + threadIdx.x;
    unsigned node = t >> 2;
    int q = t & 3;
    if (node >= NN) return;
    float d1 = rsqrtf((float)(g_cnt1[node] + 1));
    float d2 = rsqrtf((float)(g_cnt2[node] + 1));
    if (q == 0) { g_dinv1[node] = d1; g_dinv2[node] = d2; }
    size_t o = (size_t)node * 16 + q * 4;
    float4 v1 = *(const float4*)(g_y1 + o);
    float4 v2 = *(const float4*)(g_y2 + o);
    v1.x *= d1; v1.y *= d1; v1.z *= d1; v1.w *= d1;
    v2.x *= d2; v2.y *= d2; v2.z *= d2; v2.w *= d2;
    *(float4*)(g_y1 + o) = v1;
    *(float4*)(g_y2 + o) = v2;
    *(float4*)(g_acc1 + o) = v1;   // self-loop seed (epilogue applies dinv)
    *(float4*)(g_acc2 + o) = v2;
}

// ---------------- quad-per-edge scatter, both graphs in one launch -------------
__global__ void k_scatter16b(const int* __restrict__ src1, const int* __restrict__ dst1,
                             const int* __restrict__ src2, const int* __restrict__ dst2) {
    unsigned t = blockIdx.x * blockDim.x + threadIdx.x;
    unsigned e = t >> 2;
    int q = t & 3;
    if (e < NE) {
        int s = src1[e], d = dst1[e];
        float4 v = *(const float4*)(g_y1 + (size_t)s * 16 + q * 4);
        red_add_v4(g_acc1 + (size_t)d * 16 + q * 4, v);
    } else if (e < 2u * NE) {
        unsigned ee = e - NE;
        int s = src2[ee], d = dst2[ee];
        float4 v = *(const float4*)(g_y2 + (size_t)s * 16 + q * 4);
        red_add_v4(g_acc2 + (size_t)d * 16 + q * 4, v);
    }
}

// ---------------- combine: relu epilogue, concat, h @ W4, write yz + acc3 seed -
__global__ void k_combine(const float* __restrict__ b1,
                          const float* __restrict__ b2,
                          const float* __restrict__ W4) {
    __shared__ float sW4[32 * NC];
    __shared__ float sb1[HH], sb2[HH];
    int tid = threadIdx.x;
    for (int t = tid; t < 32 * NC; t += blockDim.x) sW4[t] = W4[t];
    if (tid < HH) { sb1[tid] = b1[tid]; sb2[tid] = b2[tid]; }
    __syncthreads();

    int i = blockIdx.x * blockDim.x + tid;
    if (i >= NN) return;

    float d1 = g_dinv1[i], d2 = g_dinv2[i];
    float h[32];
    const float* a1 = &g_acc1[(size_t)i * 16];
    const float* a2 = &g_acc2[(size_t)i * 16];
#pragma unroll
    for (int j = 0; j < 16; j++) {
        h[j]      = fmaxf(d1 * a1[j] + sb1[j], 0.f);
        h[16 + j] = fmaxf(d2 * a2[j] + sb2[j], 0.f);
    }

    float z[NC];
#pragma unroll
    for (int c = 0; c < NC; c++) z[c] = 0.f;
#pragma unroll
    for (int j = 0; j < 32; j++) {
        float hj = h[j];
#pragma unroll
        for (int c = 0; c < NC; c++) z[c] += hj * sW4[j * NC + c];
    }

    float* o = &g_yz[(size_t)i * 12];
    float* a = &g_acc3[(size_t)i * 12];
#pragma unroll
    for (int c = 0; c < NC; c++) {
        float yz = d1 * z[c];
        o[c] = yz;
        a[c] = yz;          // self-loop seed (epilogue applies dinv)
    }
    o[10] = 0.f; o[11] = 0.f;
    a[10] = 0.f; a[11] = 0.f;
}

// ---------------- 3-lanes-per-edge scatter for 12-padded logits ----------------
__global__ void k_scatter10q(const int* __restrict__ src,
                             const int* __restrict__ dst) {
    unsigned t = blockIdx.x * blockDim.x + threadIdx.x;
    unsigned e = t / 3u;
    int q = (int)(t - e * 3u);
    if (e >= NE) return;
    int s = src[e], d = dst[e];
    float4 v = *(const float4*)(&g_yz[(size_t)s * 12] + q * 4);
    red_add_v4(&g_acc3[(size_t)d * 12] + q * 4, v);
}

// ---------------- final: conv3 epilogue + log_softmax ----------------
__global__ void k_final(const float* __restrict__ b4, float* __restrict__ out) {
    __shared__ float sb4[NC];
    if (threadIdx.x < NC) sb4[threadIdx.x] = b4[threadIdx.x];
    __syncthreads();
    int i = blockIdx.x * blockDim.x + threadIdx.x;
    if (i >= NN) return;

    float d1 = g_dinv1[i];
    float l[NC];
    const float* a = &g_acc3[(size_t)i * 12];
#pragma unroll
    for (int c = 0; c < NC; c++) l[c] = d1 * a[c] + sb4[c];

    float m = l[0];
#pragma unroll
    for (int c = 1; c < NC; c++) m = fmaxf(m, l[c]);
    float s = 0.f;
#pragma unroll
    for (int c = 0; c < NC; c++) s += expf(l[c] - m);
    float lse = m + logf(s);
#pragma unroll
    for (int c = 0; c < NC; c++) out[(size_t)i * NC + c] = l[c] - lse;
}

// ---------------- launch ----------------
extern "C" void kernel_launch(void* const* d_in, const int* in_sizes, int n_in,
                              void* d_out, int out_size) {
    const float* x  = (const float*)d_in[0];
    const int*   ei = (const int*)d_in[1];   // [2, NE] int32: row0 src, row1 dst
    const int*   tp = (const int*)d_in[2];
    const float* W1 = (const float*)d_in[3];
    const float* b1 = (const float*)d_in[4];
    const float* W2 = (const float*)d_in[5];
    const float* b2 = (const float*)d_in[6];
    const float* W4 = (const float*)d_in[7];
    const float* b4 = (const float*)d_in[8];
    float* out = (float*)d_out;

    k_zero<<<256, 256>>>();

    k_fused<<<CNT_BLKS + GEMM_BLKS, 128>>>(x, W1, W2, ei + NE, tp + NE);

    k_scale<<<(4 * NN + 255) / 256, 256>>>();

    k_scatter16b<<<(8u * NE + 255) / 256, 256>>>(ei, ei + NE, tp, tp + NE);

    k_combine<<<(NN + 255) / 256, 256>>>(b1, b2, W4);

    k_scatter10q<<<(3u * NE + 255) / 256, 256>>>(ei, ei + NE);

    k_final<<<(NN + 255) / 256, 256>>>(b4, out);
}

// round 10
// speedup vs baseline: 1.9651x; 1.1154x over previous
#include <cuda_runtime.h>
#include <math.h>

#define NN 100000
#define NE 3200000
#define NF 128
#define HH 16
#define NC 10

#define GEMM_BLKS ((NN + 127) / 128)                  // 782, 128 nodes/block, 1 thr/node
#define CNT_BLKS  ((2 * (NE / 4) + 127) / 128)        // 12500, int4 edge loads

// ---------------- device scratch ----------------
__device__ int   g_cnt1[NN];
__device__ int   g_cnt2[NN];
__device__ float g_dinv1[NN];
__device__ float g_dinv2[NN];
__device__ __align__(16) float g_y1[NN * 16];   // dinv1[i]*(x@W1)[i] after k_scale
__device__ __align__(16) float g_y2[NN * 16];
__device__ __align__(16) float g_acc1[NN * 16]; // seed = y (self-loop), + scatter
__device__ __align__(16) float g_acc2[NN * 16];
__device__ __align__(16) float g_yz[NN * 12];   // dinv1[i]*(h@W4)[i], stride 12
__device__ __align__(16) float g_acc3[NN * 12]; // seed = yz, + scatter

// 16-byte vector reduction straight to L2 (sm_90+).
__device__ __forceinline__ void red_add_v4(float* p, float4 v) {
    asm volatile("red.global.add.v4.f32 [%0], {%1,%2,%3,%4};"
                 :: "l"(__cvta_generic_to_global(p)),
                    "f"(v.x), "f"(v.y), "f"(v.z), "f"(v.w)
                 : "memory");
}

// ---------------- zero degree counters only ----------------
__global__ void k_zero() {
    int i = blockIdx.x * blockDim.x + threadIdx.x;
    int stride = gridDim.x * blockDim.x;
    for (int t = i; t < NN; t += stride) { g_cnt1[t] = 0; g_cnt2[t] = 0; }
}

// ---------------- fused: [0..GEMM_BLKS) dual GEMM | rest: degree count ----------
// GEMM blocks FIRST so wave 1 holds both kinds -> FFMA pipe (GEMM) overlaps the
// REDG pipe (count) instead of serializing.
__global__ void __launch_bounds__(128) k_fused(
        const float* __restrict__ x,
        const float* __restrict__ W1,
        const float* __restrict__ W2,
        const int* __restrict__ dst1,
        const int* __restrict__ dst2) {
    __shared__ float Ws[NF * 32];
    int tid = threadIdx.x;

    if (blockIdx.x >= GEMM_BLKS) {
        int id = (blockIdx.x - GEMM_BLKS) * 128 + tid;   // int4 index
        const int Q = NE / 4;                            // 800000
        if (id < Q) {
            int4 d = __ldg(&((const int4*)dst1)[id]);
            atomicAdd(&g_cnt1[d.x], 1);
            atomicAdd(&g_cnt1[d.y], 1);
            atomicAdd(&g_cnt1[d.z], 1);
            atomicAdd(&g_cnt1[d.w], 1);
        } else if (id < 2 * Q) {
            int4 d = __ldg(&((const int4*)dst2)[id - Q]);
            atomicAdd(&g_cnt2[d.x], 1);
            atomicAdd(&g_cnt2[d.y], 1);
            atomicAdd(&g_cnt2[d.z], 1);
            atomicAdd(&g_cnt2[d.w], 1);
        }
        return;
    }

    // ---- GEMM part ----
    for (int idx = tid; idx < NF * 32; idx += 128) {
        int k = idx >> 5, j = idx & 31;
        Ws[idx] = (j < HH) ? W1[k * HH + j] : W2[k * HH + (j - HH)];
    }
    __syncthreads();

    int i = blockIdx.x * 128 + tid;
    if (i >= NN) return;

    float acc[32];
#pragma unroll
    for (int j = 0; j < 32; j++) acc[j] = 0.f;

    const float4* xrow = (const float4*)(x + (size_t)i * NF);
#pragma unroll 2
    for (int kk = 0; kk < NF / 4; kk++) {
        float4 xv = xrow[kk];
        const float* w = &Ws[(kk * 4) * 32];
#pragma unroll
        for (int j = 0; j < 32; j++) acc[j] += xv.x * w[j];
        w += 32;
#pragma unroll
        for (int j = 0; j < 32; j++) acc[j] += xv.y * w[j];
        w += 32;
#pragma unroll
        for (int j = 0; j < 32; j++) acc[j] += xv.z * w[j];
        w += 32;
#pragma unroll
        for (int j = 0; j < 32; j++) acc[j] += xv.w * w[j];
    }

    float* o1 = &g_y1[(size_t)i * 16];
    float* o2 = &g_y2[(size_t)i * 16];
#pragma unroll
    for (int q = 0; q < 4; q++) {
        *(float4*)(o1 + 4 * q) = make_float4(acc[4 * q], acc[4 * q + 1],
                                             acc[4 * q + 2], acc[4 * q + 3]);
        *(float4*)(o2 + 4 * q) = make_float4(acc[16 + 4 * q], acc[16 + 4 * q + 1],
                                             acc[16 + 4 * q + 2], acc[16 + 4 * q + 3]);
    }
}

// ---------------- scale: dinv from counts; y *= dinv; acc seed = y -------------
__global__ void k_scale() {
    unsigned t = blockIdx.x * blockDim.x + threadIdx.x;
    unsigned node = t >> 2;
    int q = t & 3;
    if (node >= NN) return;
    float d1 = rsqrtf((float)(g_cnt1[node] + 1));
    float d2 = rsqrtf((float)(g_cnt2[node] + 1));
    if (q == 0) { g_dinv1[node] = d1; g_dinv2[node] = d2; }
    size_t o = (size_t)node * 16 + q * 4;
    float4 v1 = *(const float4*)(g_y1 + o);
    float4 v2 = *(const float4*)(g_y2 + o);
    v1.x *= d1; v1.y *= d1; v1.z *= d1; v1.w *= d1;
    v2.x *= d2; v2.y *= d2; v2.z *= d2; v2.w *= d2;
    *(float4*)(g_y1 + o) = v1;
    *(float4*)(g_y2 + o) = v2;
    *(float4*)(g_acc1 + o) = v1;   // self-loop seed (epilogue applies dinv)
    *(float4*)(g_acc2 + o) = v2;
}

// ---------------- quad-per-edge scatter, both graphs in one launch -------------
__global__ void __launch_bounds__(512) k_scatter16b(
        const int* __restrict__ src1, const int* __restrict__ dst1,
        const int* __restrict__ src2, const int* __restrict__ dst2) {
    unsigned t = blockIdx.x * 512u + threadIdx.x;
    unsigned e = t >> 2;
    int q = t & 3;
    if (e < NE) {
        int s = __ldg(src1 + e), d = __ldg(dst1 + e);
        float4 v = *(const float4*)(g_y1 + (size_t)s * 16 + q * 4);
        red_add_v4(g_acc1 + (size_t)d * 16 + q * 4, v);
    } else if (e < 2u * NE) {
        unsigned ee = e - NE;
        int s = __ldg(src2 + ee), d = __ldg(dst2 + ee);
        float4 v = *(const float4*)(g_y2 + (size_t)s * 16 + q * 4);
        red_add_v4(g_acc2 + (size_t)d * 16 + q * 4, v);
    }
}

// ---------------- combine: relu epilogue, concat, h @ W4, write yz + acc3 seed -
__global__ void k_combine(const float* __restrict__ b1,
                          const float* __restrict__ b2,
                          const float* __restrict__ W4) {
    __shared__ float sW4[32 * NC];
    __shared__ float sb1[HH], sb2[HH];
    int tid = threadIdx.x;
    for (int t = tid; t < 32 * NC; t += blockDim.x) sW4[t] = W4[t];
    if (tid < HH) { sb1[tid] = b1[tid]; sb2[tid] = b2[tid]; }
    __syncthreads();

    int i = blockIdx.x * blockDim.x + tid;
    if (i >= NN) return;

    float d1 = g_dinv1[i], d2 = g_dinv2[i];
    float h[32];
    const float* a1 = &g_acc1[(size_t)i * 16];
    const float* a2 = &g_acc2[(size_t)i * 16];
#pragma unroll
    for (int j = 0; j < 16; j++) {
        h[j]      = fmaxf(d1 * a1[j] + sb1[j], 0.f);
        h[16 + j] = fmaxf(d2 * a2[j] + sb2[j], 0.f);
    }

    float z[NC];
#pragma unroll
    for (int c = 0; c < NC; c++) z[c] = 0.f;
#pragma unroll
    for (int j = 0; j < 32; j++) {
        float hj = h[j];
#pragma unroll
        for (int c = 0; c < NC; c++) z[c] += hj * sW4[j * NC + c];
    }

    float* o = &g_yz[(size_t)i * 12];
    float* a = &g_acc3[(size_t)i * 12];
#pragma unroll
    for (int c = 0; c < NC; c++) {
        float yz = d1 * z[c];
        o[c] = yz;
        a[c] = yz;          // self-loop seed (epilogue applies dinv)
    }
    o[10] = 0.f; o[11] = 0.f;
    a[10] = 0.f; a[11] = 0.f;
}

// ---------------- 3-lanes-per-edge scatter for 12-padded logits ----------------
__global__ void __launch_bounds__(384) k_scatter10q(const int* __restrict__ src,
                                                    const int* __restrict__ dst) {
    unsigned t = blockIdx.x * 384u + threadIdx.x;
    unsigned e = t / 3u;
    int q = (int)(t - e * 3u);
    if (e >= NE) return;
    int s = __ldg(src + e), d = __ldg(dst + e);
    float4 v = *(const float4*)(&g_yz[(size_t)s * 12] + q * 4);
    red_add_v4(&g_acc3[(size_t)d * 12] + q * 4, v);
}

// ---------------- final: conv3 epilogue + log_softmax ----------------
__global__ void k_final(const float* __restrict__ b4, float* __restrict__ out) {
    __shared__ float sb4[NC];
    if (threadIdx.x < NC) sb4[threadIdx.x] = b4[threadIdx.x];
    __syncthreads();
    int i = blockIdx.x * blockDim.x + threadIdx.x;
    if (i >= NN) return;

    float d1 = g_dinv1[i];
    float l[NC];
    const float* a = &g_acc3[(size_t)i * 12];
#pragma unroll
    for (int c = 0; c < NC; c++) l[c] = d1 * a[c] + sb4[c];

    float m = l[0];
#pragma unroll
    for (int c = 1; c < NC; c++) m = fmaxf(m, l[c]);
    float s = 0.f;
#pragma unroll
    for (int c = 0; c < NC; c++) s += expf(l[c] - m);
    float lse = m + logf(s);
#pragma unroll
    for (int c = 0; c < NC; c++) out[(size_t)i * NC + c] = l[c] - lse;
}

// ---------------- launch ----------------
extern "C" void kernel_launch(void* const* d_in, const int* in_sizes, int n_in,
                              void* d_out, int out_size) {
    const float* x  = (const float*)d_in[0];
    const int*   ei = (const int*)d_in[1];   // [2, NE] int32: row0 src, row1 dst
    const int*   tp = (const int*)d_in[2];
    const float* W1 = (const float*)d_in[3];
    const float* b1 = (const float*)d_in[4];
    const float* W2 = (const float*)d_in[5];
    const float* b2 = (const float*)d_in[6];
    const float* W4 = (const float*)d_in[7];
    const float* b4 = (const float*)d_in[8];
    float* out = (float*)d_out;

    k_zero<<<256, 256>>>();

    k_fused<<<GEMM_BLKS + CNT_BLKS, 128>>>(x, W1, W2, ei + NE, tp + NE);

    k_scale<<<(4 * NN + 255) / 256, 256>>>();

    k_scatter16b<<<(8u * NE + 511) / 512, 512>>>(ei, ei + NE, tp, tp + NE);

    k_combine<<<(NN + 255) / 256, 256>>>(b1, b2, W4);

    k_scatter10q<<<(3u * NE + 383) / 384, 384>>>(ei, ei + NE);

    k_final<<<(NN + 255) / 256, 256>>>(b4, out);
}

// round 11
// speedup vs baseline: 2.0270x; 1.0315x over previous
#include <cuda_runtime.h>
#include <math.h>

#define NN 100000
#define NE 3200000
#define NF 128
#define HH 16
#define NC 10

#define GEMM_BLKS ((NN + 127) / 128)                  // 782, 128 nodes/block, 1 thr/node
#define CNT_BLKS  ((2 * (NE / 4) + 127) / 128)        // 12500, int4 edge loads

// ---------------- device scratch (zero-initialized at module load) -------------
__device__ int   g_cnt1[NN];    // re-zeroed by k_scale after use -> clean each call
__device__ int   g_cnt2[NN];
__device__ float g_dinv1[NN];
__device__ float g_dinv2[NN];
__device__ __align__(16) float g_y1[NN * 16];   // dinv1[i]*(x@W1)[i] after k_scale
__device__ __align__(16) float g_y2[NN * 16];
__device__ __align__(16) float g_acc1[NN * 16]; // seed = y (self-loop), + scatter
__device__ __align__(16) float g_acc2[NN * 16];
__device__ __align__(16) float g_yz[NN * 12];   // dinv1[i]*(h@W4)[i], stride 12
__device__ __align__(16) float g_acc3[NN * 12]; // seed = yz, + scatter

// 16-byte vector reduction straight to L2 (sm_90+).
__device__ __forceinline__ void red_add_v4(float* p, float4 v) {
    asm volatile("red.global.add.v4.f32 [%0], {%1,%2,%3,%4};"
                 :: "l"(__cvta_generic_to_global(p)),
                    "f"(v.x), "f"(v.y), "f"(v.z), "f"(v.w)
                 : "memory");
}

// ---------------- fused: [0..GEMM_BLKS) dual GEMM | rest: degree count ----------
// GEMM blocks FIRST so wave 1 holds both kinds -> FFMA pipe (GEMM) overlaps the
// REDG pipe (count) instead of serializing.
__global__ void __launch_bounds__(128) k_fused(
        const float* __restrict__ x,
        const float* __restrict__ W1,
        const float* __restrict__ W2,
        const int* __restrict__ dst1,
        const int* __restrict__ dst2) {
    __shared__ float Ws[NF * 32];
    int tid = threadIdx.x;

    if (blockIdx.x >= GEMM_BLKS) {
        int id = (blockIdx.x - GEMM_BLKS) * 128 + tid;   // int4 index
        const int Q = NE / 4;                            // 800000
        if (id < Q) {
            int4 d = __ldg(&((const int4*)dst1)[id]);
            atomicAdd(&g_cnt1[d.x], 1);
            atomicAdd(&g_cnt1[d.y], 1);
            atomicAdd(&g_cnt1[d.z], 1);
            atomicAdd(&g_cnt1[d.w], 1);
        } else if (id < 2 * Q) {
            int4 d = __ldg(&((const int4*)dst2)[id - Q]);
            atomicAdd(&g_cnt2[d.x], 1);
            atomicAdd(&g_cnt2[d.y], 1);
            atomicAdd(&g_cnt2[d.z], 1);
            atomicAdd(&g_cnt2[d.w], 1);
        }
        return;
    }

    // ---- GEMM part ----
    for (int idx = tid; idx < NF * 32; idx += 128) {
        int k = idx >> 5, j = idx & 31;
        Ws[idx] = (j < HH) ? W1[k * HH + j] : W2[k * HH + (j - HH)];
    }
    __syncthreads();

    int i = blockIdx.x * 128 + tid;
    if (i >= NN) return;

    float acc[32];
#pragma unroll
    for (int j = 0; j < 32; j++) acc[j] = 0.f;

    const float4* xrow = (const float4*)(x + (size_t)i * NF);
#pragma unroll 2
    for (int kk = 0; kk < NF / 4; kk++) {
        float4 xv = xrow[kk];
        const float* w = &Ws[(kk * 4) * 32];
#pragma unroll
        for (int j = 0; j < 32; j++) acc[j] += xv.x * w[j];
        w += 32;
#pragma unroll
        for (int j = 0; j < 32; j++) acc[j] += xv.y * w[j];
        w += 32;
#pragma unroll
        for (int j = 0; j < 32; j++) acc[j] += xv.z * w[j];
        w += 32;
#pragma unroll
        for (int j = 0; j < 32; j++) acc[j] += xv.w * w[j];
    }

    float* o1 = &g_y1[(size_t)i * 16];
    float* o2 = &g_y2[(size_t)i * 16];
#pragma unroll
    for (int q = 0; q < 4; q++) {
        *(float4*)(o1 + 4 * q) = make_float4(acc[4 * q], acc[4 * q + 1],
                                             acc[4 * q + 2], acc[4 * q + 3]);
        *(float4*)(o2 + 4 * q) = make_float4(acc[16 + 4 * q], acc[16 + 4 * q + 1],
                                             acc[16 + 4 * q + 2], acc[16 + 4 * q + 3]);
    }
}

// ---------------- scale: dinv from counts; y *= dinv; acc seed = y; re-zero cnt -
// quad layout: 4 lanes per node, coalesced float4.
__global__ void k_scale() {
    unsigned t = blockIdx.x * blockDim.x + threadIdx.x;
    unsigned node = t >> 2;
    int q = t & 3;
    if (node >= NN) return;
    float d1 = rsqrtf((float)(g_cnt1[node] + 1));
    float d2 = rsqrtf((float)(g_cnt2[node] + 1));
    if (q == 0) {
        g_dinv1[node] = d1;
        g_dinv2[node] = d2;
        g_cnt1[node] = 0;   // leave counters clean for the next call/replay
        g_cnt2[node] = 0;
    }
    size_t o = (size_t)node * 16 + q * 4;
    float4 v1 = *(const float4*)(g_y1 + o);
    float4 v2 = *(const float4*)(g_y2 + o);
    v1.x *= d1; v1.y *= d1; v1.z *= d1; v1.w *= d1;
    v2.x *= d2; v2.y *= d2; v2.z *= d2; v2.w *= d2;
    *(float4*)(g_y1 + o) = v1;
    *(float4*)(g_y2 + o) = v2;
    *(float4*)(g_acc1 + o) = v1;   // self-loop seed (epilogue applies dinv)
    *(float4*)(g_acc2 + o) = v2;
}

// ---------------- quad-per-edge scatter, both graphs in one launch -------------
__global__ void __launch_bounds__(256) k_scatter16b(
        const int* __restrict__ src1, const int* __restrict__ dst1,
        const int* __restrict__ src2, const int* __restrict__ dst2) {
    unsigned t = blockIdx.x * 256u + threadIdx.x;
    unsigned e = t >> 2;
    int q = t & 3;
    if (e < NE) {
        int s = __ldg(src1 + e), d = __ldg(dst1 + e);
        float4 v = *(const float4*)(g_y1 + (size_t)s * 16 + q * 4);
        red_add_v4(g_acc1 + (size_t)d * 16 + q * 4, v);
    } else if (e < 2u * NE) {
        unsigned ee = e - NE;
        int s = __ldg(src2 + ee), d = __ldg(dst2 + ee);
        float4 v = *(const float4*)(g_y2 + (size_t)s * 16 + q * 4);
        red_add_v4(g_acc2 + (size_t)d * 16 + q * 4, v);
    }
}

// ---------------- combine: relu epilogue, concat, h @ W4, write yz + acc3 seed -
__global__ void k_combine(const float* __restrict__ b1,
                          const float* __restrict__ b2,
                          const float* __restrict__ W4) {
    __shared__ float sW4[32 * NC];
    __shared__ float sb1[HH], sb2[HH];
    int tid = threadIdx.x;
    for (int t = tid; t < 32 * NC; t += blockDim.x) sW4[t] = W4[t];
    if (tid < HH) { sb1[tid] = b1[tid]; sb2[tid] = b2[tid]; }
    __syncthreads();

    int i = blockIdx.x * blockDim.x + tid;
    if (i >= NN) return;

    float d1 = g_dinv1[i], d2 = g_dinv2[i];
    float h[32];
    const float* a1 = &g_acc1[(size_t)i * 16];
    const float* a2 = &g_acc2[(size_t)i * 16];
#pragma unroll
    for (int j = 0; j < 16; j++) {
        h[j]      = fmaxf(d1 * a1[j] + sb1[j], 0.f);
        h[16 + j] = fmaxf(d2 * a2[j] + sb2[j], 0.f);
    }

    float z[NC];
#pragma unroll
    for (int c = 0; c < NC; c++) z[c] = 0.f;
#pragma unroll
    for (int j = 0; j < 32; j++) {
        float hj = h[j];
#pragma unroll
        for (int c = 0; c < NC; c++) z[c] += hj * sW4[j * NC + c];
    }

    float* o = &g_yz[(size_t)i * 12];
    float* a = &g_acc3[(size_t)i * 12];
#pragma unroll
    for (int c = 0; c < NC; c++) {
        float yz = d1 * z[c];
        o[c] = yz;
        a[c] = yz;          // self-loop seed (epilogue applies dinv)
    }
    o[10] = 0.f; o[11] = 0.f;
    a[10] = 0.f; a[11] = 0.f;
}

// ---------------- 3-lanes-per-edge scatter for 12-padded logits ----------------
__global__ void __launch_bounds__(384) k_scatter10q(const int* __restrict__ src,
                                                    const int* __restrict__ dst) {
    unsigned t = blockIdx.x * 384u + threadIdx.x;
    unsigned e = t / 3u;
    int q = (int)(t - e * 3u);
    if (e >= NE) return;
    int s = __ldg(src + e), d = __ldg(dst + e);
    float4 v = *(const float4*)(&g_yz[(size_t)s * 12] + q * 4);
    red_add_v4(&g_acc3[(size_t)d * 12] + q * 4, v);
}

// ---------------- final: conv3 epilogue + log_softmax ----------------
__global__ void k_final(const float* __restrict__ b4, float* __restrict__ out) {
    __shared__ float sb4[NC];
    if (threadIdx.x < NC) sb4[threadIdx.x] = b4[threadIdx.x];
    __syncthreads();
    int i = blockIdx.x * blockDim.x + threadIdx.x;
    if (i >= NN) return;

    float d1 = g_dinv1[i];
    float l[NC];
    const float* a = &g_acc3[(size_t)i * 12];
#pragma unroll
    for (int c = 0; c < NC; c++) l[c] = d1 * a[c] + sb4[c];

    float m = l[0];
#pragma unroll
    for (int c = 1; c < NC; c++) m = fmaxf(m, l[c]);
    float s = 0.f;
#pragma unroll
    for (int c = 0; c < NC; c++) s += expf(l[c] - m);
    float lse = m + logf(s);
#pragma unroll
    for (int c = 0; c < NC; c++) out[(size_t)i * NC + c] = l[c] - lse;
}

// ---------------- launch ----------------
extern "C" void kernel_launch(void* const* d_in, const int* in_sizes, int n_in,
                              void* d_out, int out_size) {
    const float* x  = (const float*)d_in[0];
    const int*   ei = (const int*)d_in[1];   // [2, NE] int32: row0 src, row1 dst
    const int*   tp = (const int*)d_in[2];
    const float* W1 = (const float*)d_in[3];
    const float* b1 = (const float*)d_in[4];
    const float* W2 = (const float*)d_in[5];
    const float* b2 = (const float*)d_in[6];
    const float* W4 = (const float*)d_in[7];
    const float* b4 = (const float*)d_in[8];
    float* out = (float*)d_out;

    k_fused<<<GEMM_BLKS + CNT_BLKS, 128>>>(x, W1, W2, ei + NE, tp + NE);

    k_scale<<<(4 * NN + 255) / 256, 256>>>();

    k_scatter16b<<<(8u * NE + 255) / 256, 256>>>(ei, ei + NE, tp, tp + NE);

    k_combine<<<(NN + 255) / 256, 256>>>(b1, b2, W4);

    k_scatter10q<<<(3u * NE + 383) / 384, 384>>>(ei, ei + NE);

    k_final<<<(NN + 255) / 256, 256>>>(b4, out);
}